// round 11
// baseline (speedup 1.0000x reference)
#include <cuda_runtime.h>
#include <cuda_bf16.h>
#include <cstdint>

constexpr int B = 32;
constexpr int A = 16384;
constexpr int C = 81;

constexpr int APB  = 32;            // anchors per block
constexpr int FPB  = APB * C;       // 2592 floats
constexpr int V4PB = FPB / 4;       // 648 float4
constexpr int WPB  = A / 32;        // 512 mask words per batch
constexpr int BPB  = A / APB;       // 512 blocks per batch

// Scratch (device globals; no allocations allowed).
__device__ float    g_maxce[B * A];         // slow path only
__device__ unsigned g_posmask[B * WPB];     // bit: depth > 0
__device__ unsigned g_zeromask[B * WPB];    // bit: v == 0
__device__ unsigned g_done[B];              // ticket counters (self-resetting)

// ---------------------------------------------------------------------------
__device__ __forceinline__ float ex2f(float x) {
    float r; asm("ex2.approx.f32 %0, %1;" : "=f"(r) : "f"(x)); return r;
}
__device__ __forceinline__ float lg2f(float x) {
    float r; asm("lg2.approx.f32 %0, %1;" : "=f"(r) : "f"(x)); return r;
}
// softplus(x) = max(x,0) + ln2 * log2(1 + 2^(-|x|*log2e));  2 MUFU + ~4 FMA.
__device__ __forceinline__ float bce(float x, float t) {
    const float LOG2E = 1.4426950408889634f;
    const float LN2   = 0.6931471805599453f;
    const float e  = ex2f(-LOG2E * fabsf(x));
    const float sp = fmaxf(x, 0.0f) + LN2 * lg2f(1.0f + e);
    return sp - t * x;
}
__device__ __forceinline__ float4 bce4(float4 x, float4 t) {
    float4 r;
    r.x = bce(x.x, t.x); r.y = bce(x.y, t.y);
    r.z = bce(x.z, t.z); r.w = bce(x.w, t.w);
    return r;
}

// Scoped atomic ticket: release publishes this block's prior writes (after
// bar.sync) with NO membar/L1 flush; acquire on the returned old value.
__device__ __forceinline__ unsigned ticket_acq_rel(unsigned* p) {
    unsigned old;
    asm volatile("atom.add.acq_rel.gpu.u32 %0, [%1], 1;"
                 : "=r"(old) : "l"(p) : "memory");
    return old;
}

// ---------------------------------------------------------------------------
// Fused kernel: BCE + per-anchor max + bitmasks; the last block of each batch
// (scoped-atomic ticket) performs hard-negative selection + row zeroing.
// ---------------------------------------------------------------------------
__global__ void __launch_bounds__(256) fused_kernel(
    const float* __restrict__ pred,
    const float* __restrict__ tgt,
    const int*   __restrict__ depth,
    const int*   __restrict__ npr_ptr,
    float*       __restrict__ out)
{
    __shared__ float s_ce[FPB];
    __shared__ float s_m[APB];
    __shared__ int   s_scan[8];
    __shared__ int   s_flag;

    const int tid  = threadIdx.x;
    const int lane = tid & 31;
    const int wid  = tid >> 5;
    const unsigned FULL = 0xffffffffu;
    const int batch = blockIdx.x >> 9;      // / BPB

    // ===================== Phase 1: streaming BCE =====================
    {
        const size_t base4 = (size_t)blockIdx.x * V4PB;
        const float4* __restrict__ p4 = reinterpret_cast<const float4*>(pred) + base4;
        const float4* __restrict__ t4 = reinterpret_cast<const float4*>(tgt)  + base4;
        float4* __restrict__ o4 = reinterpret_cast<float4*>(out) + base4;

        const bool has2 = (tid + 512) < V4PB;   // 648 = 256+256+136
        const float4 x0 = __ldcs(&p4[tid]);
        const float4 T0 = __ldcs(&t4[tid]);
        const float4 x1 = __ldcs(&p4[tid + 256]);
        const float4 T1 = __ldcs(&t4[tid + 256]);
        float4 x2, T2;
        if (has2) { x2 = __ldcs(&p4[tid + 512]); T2 = __ldcs(&t4[tid + 512]); }

        const float4 c0 = bce4(x0, T0);
        __stcs(&o4[tid], c0);
        *reinterpret_cast<float4*>(&s_ce[tid * 4]) = c0;
        const float4 c1 = bce4(x1, T1);
        __stcs(&o4[tid + 256], c1);
        *reinterpret_cast<float4*>(&s_ce[(tid + 256) * 4]) = c1;
        if (has2) {
            const float4 c2 = bce4(x2, T2);
            __stcs(&o4[tid + 512], c2);
            *reinterpret_cast<float4*>(&s_ce[(tid + 512) * 4]) = c2;
        }
    }
    __syncthreads();

    // ===================== Phase 2: per-anchor max =====================
    const int gbase = blockIdx.x * APB;
#pragma unroll
    for (int k = 0; k < APB / 8; k++) {
        const int a = wid + k * 8;
        float m = s_ce[a * C + lane];
        if (lane + 32 < C) m = fmaxf(m, s_ce[a * C + lane + 32]);
        if (lane + 64 < C) m = fmaxf(m, s_ce[a * C + lane + 64]);
#pragma unroll
        for (int off = 16; off; off >>= 1)
            m = fmaxf(m, __shfl_xor_sync(FULL, m, off));
        if (lane == 0) s_m[a] = m;
    }
    __syncthreads();

    if (wid == 0) {
        const int g = gbase + lane;
        const int d = depth[g];
        const float meff = (d != 0) ? 0.0f : s_m[lane];
        g_maxce[g] = meff;
        const unsigned posb  = __ballot_sync(FULL, d > 0);
        const unsigned zerob = __ballot_sync(FULL, meff == 0.0f);
        if (lane == 0) {
            g_posmask[blockIdx.x]  = posb;
            g_zeromask[blockIdx.x] = zerob;
        }
    }
    __syncthreads();   // all writes happen-before lane0's release atomic

    // ===================== Ticket (no membar, no L1 flush) ==============
    if (tid == 0)
        s_flag = (ticket_acq_rel(&g_done[batch]) == BPB - 1);
    __syncthreads();
    if (!s_flag) return;

    const int b = batch;
    if (tid == 0) g_done[b] = 0;            // reset for next graph replay

    // ===================== Selection (256 threads, 2 words each) ========
    const int w0 = b * WPB + tid * 2;
    const unsigned p0 = g_posmask[w0],  p1 = g_posmask[w0 + 1];
    const unsigned z0 = g_zeromask[w0], z1 = g_zeromask[w0 + 1];
    const int myz  = __popc(z0) + __popc(z1);
    const int pack = myz | ((__popc(p0) + __popc(p1)) << 16);

    // single packed inclusive scan (zeros low16, pos high16; no carry)
    int inc = pack;
#pragma unroll
    for (int off = 1; off < 32; off <<= 1) {
        const int n = __shfl_up_sync(FULL, inc, off);
        if (lane >= off) inc += n;
    }
    if (lane == 31) s_scan[wid] = inc;
    __syncthreads();
    int total;
    if (wid == 0) {
        int y = (lane < 8) ? s_scan[lane] : 0;
        const int orig = y;
#pragma unroll
        for (int off = 1; off < 8; off <<= 1) {
            const int n = __shfl_up_sync(FULL, y, off);
            if (lane >= off) y += n;
        }
        if (lane < 8) s_scan[lane] = y - orig;   // exclusive warp bases
    }
    __syncthreads();
    {
        // recompute grand total from warp 7 base + its inclusive is messy;
        // broadcast via shared instead:
        __shared__ int s_tot;
        if (tid == 255) s_tot = s_scan[7] + inc; // last thread: base + my inclusive
        __syncthreads();
        total = s_tot;
    }

    const int excl   = s_scan[wid] + (inc - pack);
    const int zbase0 = excl & 0xFFFF;
    const int zeros  = total & 0xFFFF;
    const int num_pos = total >> 16;
    const int cgt = A - zeros;

    const int ratio = npr_ptr ? *npr_ptr : 3;
    int num_neg = ratio * num_pos;
    if (num_neg > A - 1) num_neg = A - 1;
    if (num_neg < 0)     num_neg = 0;

    if (num_neg == 0 || num_neg > cgt) {
        // -------- FAST PATH: v* == 0 (or no negatives) --------
        const bool have_neg = (num_neg > 0);
        const int  r_ties   = have_neg ? (num_neg - cgt) : 0;
#pragma unroll
        for (int k = 0; k < 2; k++) {
            const unsigned zb = k ? z1 : z0;
            const unsigned pb = k ? p1 : p0;
            const int zbase = k ? (zbase0 + __popc(z0)) : zbase0;
            const int abase = (tid * 2 + k) * 32;
#pragma unroll 4
            for (int bit = 0; bit < 32; bit++) {
                const bool zero = (zb >> bit) & 1u;
                const bool pos  = (pb >> bit) & 1u;
                bool neg;
                if (!have_neg)  neg = false;
                else if (!zero) neg = true;
                else            neg = (zbase + __popc(zb & ((1u << bit) - 1))) < r_ties;
                if (!(pos || neg)) {
                    float* row = out + ((size_t)b * A + abase + bit) * C;
#pragma unroll
                    for (int c = 0; c < C; c++) row[c] = 0.0f;
                }
            }
        }
        return;
    }

    // -------- SLOW PATH (rare): radix select, re-reading g_maxce from L2 ---
    __shared__ unsigned long long s_red[8];
    const uint32_t* vrow = reinterpret_cast<const uint32_t*>(g_maxce) + (size_t)b * A;

    uint32_t vstar = 0;
    int r_ties = 0;
    {
        uint32_t prefix = 0, pmask = 0;
        int rem = num_neg;
        for (int bit = 30; bit >= 0; bit -= 2) {
            unsigned long long pc = 0;
            for (int k = 0; k < 64; k++) {
                const uint32_t v = vrow[tid * 64 + k];
                if ((v & pmask) == prefix) {
                    const unsigned two = (v >> bit) & 3u;
                    pc += (two == 3u) ? (1ull << 42)
                        : (two == 2u) ? (1ull << 21)
                        : (two == 1u) ? 1ull : 0ull;
                }
            }
#pragma unroll
            for (int off = 16; off; off >>= 1) pc += __shfl_xor_sync(FULL, pc, off);
            if (lane == 0) s_red[wid] = pc;
            __syncthreads();
            if (wid == 0) {
                unsigned long long y = (lane < 8) ? s_red[lane] : 0ull;
#pragma unroll
                for (int off = 4; off; off >>= 1) y += __shfl_xor_sync(FULL, y, off);
                if (lane == 0) s_red[0] = y;
            }
            __syncthreads();
            pc = s_red[0];
            __syncthreads();

            const int c3 = (int)((pc >> 42) & 0x1FFFFF);
            const int c2 = (int)((pc >> 21) & 0x1FFFFF);
            const int c1 = (int)( pc        & 0x1FFFFF);
            uint32_t sel;
            if      (c3 >= rem)           { sel = 3u; }
            else if (c3 + c2 >= rem)      { sel = 2u; rem -= c3; }
            else if (c3 + c2 + c1 >= rem) { sel = 1u; rem -= c3 + c2; }
            else                          { sel = 0u; rem -= c3 + c2 + c1; }
            prefix |= sel << bit;
            pmask  |= 3u << bit;
        }
        vstar  = prefix;
        r_ties = rem;
    }

    int myt = 0;
    for (int k = 0; k < 64; k++) myt += (vrow[tid * 64 + k] == vstar);
    int ts = myt;
#pragma unroll
    for (int off = 1; off < 32; off <<= 1) {
        const int n = __shfl_up_sync(FULL, ts, off);
        if (lane >= off) ts += n;
    }
    if (lane == 31) s_scan[wid] = ts;
    __syncthreads();
    if (wid == 0) {
        int y = (lane < 8) ? s_scan[lane] : 0;
        const int orig = y;
#pragma unroll
        for (int off = 1; off < 8; off <<= 1) {
            const int n = __shfl_up_sync(FULL, y, off);
            if (lane >= off) y += n;
        }
        if (lane < 8) s_scan[lane] = y - orig;
    }
    __syncthreads();
    int tie_idx = s_scan[wid] + (ts - myt);

    for (int k = 0; k < 64; k++) {
        const int a = tid * 64 + k;
        const uint32_t v = vrow[a];
        const bool tie = (v == vstar);
        const bool neg = (v > vstar) || (tie && tie_idx < r_ties);
        if (tie) tie_idx++;
        const bool pos = (g_posmask[b * WPB + (a >> 5)] >> (a & 31)) & 1u;
        if (!(pos || neg)) {
            float* row = out + ((size_t)b * A + a) * C;
#pragma unroll
            for (int c = 0; c < C; c++) row[c] = 0.0f;
        }
    }
}

// ---------------------------------------------------------------------------
extern "C" void kernel_launch(void* const* d_in, const int* in_sizes, int n_in,
                              void* d_out, int out_size)
{
    const float* pred  = (const float*)d_in[0];
    const float* tgt   = (const float*)d_in[1];
    const int*   depth = (const int*)d_in[2];
    const int*   npr   = (n_in >= 4) ? (const int*)d_in[3] : nullptr;
    float* out = (float*)d_out;

    fused_kernel<<<(B * A) / APB, 256>>>(pred, tgt, depth, npr, out);
}

// round 12
// speedup vs baseline: 1.0900x; 1.0900x over previous
#include <cuda_runtime.h>
#include <cuda_bf16.h>
#include <cstdint>

constexpr int B = 32;
constexpr int A = 16384;
constexpr int C = 81;

constexpr int APB  = 32;            // anchors per ce block
constexpr int FPB  = APB * C;       // 2592 floats
constexpr int V4PB = FPB / 4;       // 648 float4
constexpr int WPB  = A / 32;        // 512 mask words per batch

// Scratch (device globals; no allocations allowed).
__device__ float    g_maxce[B * A];         // slow path only
__device__ unsigned g_posmask[B * WPB];     // bit: depth > 0
__device__ unsigned g_zeromask[B * WPB];    // bit: v == 0  (v = masked max_ce)

// ---------------------------------------------------------------------------
__device__ __forceinline__ float ex2f(float x) {
    float r; asm("ex2.approx.f32 %0, %1;" : "=f"(r) : "f"(x)); return r;
}
__device__ __forceinline__ float lg2f(float x) {
    float r; asm("lg2.approx.f32 %0, %1;" : "=f"(r) : "f"(x)); return r;
}
// softplus(x) = max(x,0) + ln2 * log2(1 + 2^(-|x|*log2e));  2 MUFU + ~4 FMA.
__device__ __forceinline__ float bce(float x, float t) {
    const float LOG2E = 1.4426950408889634f;
    const float LN2   = 0.6931471805599453f;
    const float e  = ex2f(-LOG2E * fabsf(x));
    const float sp = fmaxf(x, 0.0f) + LN2 * lg2f(1.0f + e);
    return sp - t * x;
}
__device__ __forceinline__ float4 bce4(float4 x, float4 t) {
    float4 r;
    r.x = bce(x.x, t.x); r.y = bce(x.y, t.y);
    r.z = bce(x.z, t.z); r.w = bce(x.w, t.w);
    return r;
}

// ---------------------------------------------------------------------------
// Kernel 1: BCE-with-logits + per-anchor max + per-batch bitmasks (proven R9).
// ---------------------------------------------------------------------------
__global__ void __launch_bounds__(256) ce_kernel(
    const float* __restrict__ pred,
    const float* __restrict__ tgt,
    const int*   __restrict__ depth,
    float*       __restrict__ out)
{
    __shared__ float s_ce[FPB];
    __shared__ float s_m[APB];

    const int tid = threadIdx.x;
    const size_t base4 = (size_t)blockIdx.x * V4PB;
    const float4* __restrict__ p4 = reinterpret_cast<const float4*>(pred) + base4;
    const float4* __restrict__ t4 = reinterpret_cast<const float4*>(tgt)  + base4;
    float4* __restrict__ o4 = reinterpret_cast<float4*>(out) + base4;

    // Front-batched loads: 648 = 256 + 256 + 136.
    const bool has2 = (tid + 512) < V4PB;
    const float4 x0 = __ldcs(&p4[tid]);
    const float4 T0 = __ldcs(&t4[tid]);
    const float4 x1 = __ldcs(&p4[tid + 256]);
    const float4 T1 = __ldcs(&t4[tid + 256]);
    float4 x2, T2;
    if (has2) { x2 = __ldcs(&p4[tid + 512]); T2 = __ldcs(&t4[tid + 512]); }

    const float4 c0 = bce4(x0, T0);
    __stcs(&o4[tid], c0);
    *reinterpret_cast<float4*>(&s_ce[tid * 4]) = c0;

    const float4 c1 = bce4(x1, T1);
    __stcs(&o4[tid + 256], c1);
    *reinterpret_cast<float4*>(&s_ce[(tid + 256) * 4]) = c1;

    if (has2) {
        const float4 c2 = bce4(x2, T2);
        __stcs(&o4[tid + 512], c2);
        *reinterpret_cast<float4*>(&s_ce[(tid + 512) * 4]) = c2;
    }
    __syncthreads();

    const int lane  = tid & 31;
    const int wid   = tid >> 5;
    const int gbase = blockIdx.x * APB;

#pragma unroll
    for (int k = 0; k < APB / 8; k++) {
        const int a = wid + k * 8;
        float m = s_ce[a * C + lane];
        if (lane + 32 < C) m = fmaxf(m, s_ce[a * C + lane + 32]);
        if (lane + 64 < C) m = fmaxf(m, s_ce[a * C + lane + 64]);
#pragma unroll
        for (int off = 16; off; off >>= 1)
            m = fmaxf(m, __shfl_xor_sync(0xffffffffu, m, off));
        if (lane == 0) s_m[a] = m;
    }
    __syncthreads();

    if (wid == 0) {
        const int g = gbase + lane;
        const int d = depth[g];
        const float meff = (d != 0) ? 0.0f : s_m[lane];
        g_maxce[g] = meff;
        const unsigned posb  = __ballot_sync(0xffffffffu, d > 0);
        const unsigned zerob = __ballot_sync(0xffffffffu, meff == 0.0f);
        if (lane == 0) {
            g_posmask[blockIdx.x]  = posb;
            g_zeromask[blockIdx.x] = zerob;
        }
    }

#if __CUDA_ARCH__ >= 900
    cudaTriggerProgrammaticLaunchCompletion();
#endif
}

// ---------------------------------------------------------------------------
// Kernel 2: ONE WARP per batch. Lane owns 16 contiguous bitmask words of each
// mask (4x LDG.128 each). Single warp scan; no __syncthreads anywhere.
// Fast path skips words via candidate filter (drop needs zero && !pos &&
// zrank >= r_ties, which hits ~1 anchor/batch).
// ---------------------------------------------------------------------------
__global__ void __launch_bounds__(32) mask_kernel(
    const int* __restrict__ npr_ptr,
    float*     __restrict__ out)
{
#if __CUDA_ARCH__ >= 900
    cudaGridDependencySynchronize();
#endif
    const int b    = blockIdx.x;
    const int lane = threadIdx.x;
    const unsigned FULL = 0xffffffffu;

    const int ratio = npr_ptr ? *npr_ptr : 3;

    // ---- load my 16 words of each bitmask (registers) ----
    uint32_t pw[16], zw[16];
    const uint4* pp = reinterpret_cast<const uint4*>(g_posmask  + b * WPB) + lane * 4;
    const uint4* zz = reinterpret_cast<const uint4*>(g_zeromask + b * WPB) + lane * 4;
#pragma unroll
    for (int q = 0; q < 4; q++) {
        const uint4 u = pp[q];
        pw[q*4+0] = u.x; pw[q*4+1] = u.y; pw[q*4+2] = u.z; pw[q*4+3] = u.w;
    }
#pragma unroll
    for (int q = 0; q < 4; q++) {
        const uint4 u = zz[q];
        zw[q*4+0] = u.x; zw[q*4+1] = u.y; zw[q*4+2] = u.z; zw[q*4+3] = u.w;
    }

    int myz = 0, myp = 0;
#pragma unroll
    for (int j = 0; j < 16; j++) { myz += __popc(zw[j]); myp += __popc(pw[j]); }

    // packed inclusive warp scan: zeros low16, pos high16 (both <= 16384)
    int inc = myz | (myp << 16);
    const int pack = inc;
#pragma unroll
    for (int off = 1; off < 32; off <<= 1) {
        const int n = __shfl_up_sync(FULL, inc, off);
        if (lane >= off) inc += n;
    }
    const int total   = __shfl_sync(FULL, inc, 31);
    const int zbase0  = (inc - pack) & 0xFFFF;   // zeros strictly before my chunk
    const int zeros   = total & 0xFFFF;
    const int num_pos = total >> 16;
    const int cgt     = A - zeros;               // count(v > 0)

    int num_neg = ratio * num_pos;
    if (num_neg > A - 1) num_neg = A - 1;
    if (num_neg < 0)     num_neg = 0;

    if (num_neg == 0 || num_neg > cgt) {
        // ---------------- FAST PATH: vstar == 0 (or no negatives) ----------
        const bool have_neg = (num_neg > 0);
        const int  r_ties   = have_neg ? (num_neg - cgt) : 0;

        int zrun = zbase0;
        const int abase0 = (b * A) + lane * 512;  // my first anchor (global)
#pragma unroll
        for (int j = 0; j < 16; j++) {
            const unsigned zb = zw[j];
            const unsigned pb = pw[j];
            unsigned cand;
            if (!have_neg) {
                cand = ~pb;                       // drop every non-positive
            } else {
                cand = zb & ~pb;                  // potential drops
                if (zrun + __popc(zb) <= r_ties)  // all zeros here still neg
                    cand = 0;
            }
            while (cand) {
                const int bit = __ffs(cand) - 1;
                cand &= cand - 1;
                bool drop = true;
                if (have_neg) {
                    const int zrank = zrun + __popc(zb & ((1u << bit) - 1));
                    drop = (zrank >= r_ties);
                }
                if (drop) {
                    float* row = out + (size_t)(abase0 + j * 32 + bit) * C;
                    for (int c = 0; c < C; c++) row[c] = 0.0f;
                }
            }
            zrun += __popc(zb);
        }
        return;
    }

    // ---------------- SLOW PATH (rare): radix select, 512 values/lane ------
    const uint32_t* vrow = reinterpret_cast<const uint32_t*>(g_maxce) + (size_t)b * A;

    uint32_t vstar = 0;
    int r_ties = 0;
    {
        uint32_t prefix = 0, pmask = 0;
        int rem = num_neg;
        for (int bit = 30; bit >= 0; bit -= 2) {
            unsigned long long pc = 0;
            for (int k = 0; k < 512; k++) {
                const uint32_t v = vrow[lane * 512 + k];
                if ((v & pmask) == prefix) {
                    const unsigned two = (v >> bit) & 3u;
                    pc += (two == 3u) ? (1ull << 42)
                        : (two == 2u) ? (1ull << 21)
                        : (two == 1u) ? 1ull : 0ull;
                }
            }
#pragma unroll
            for (int off = 16; off; off >>= 1) pc += __shfl_xor_sync(FULL, pc, off);

            const int c3 = (int)((pc >> 42) & 0x1FFFFF);
            const int c2 = (int)((pc >> 21) & 0x1FFFFF);
            const int c1 = (int)( pc        & 0x1FFFFF);
            uint32_t sel;
            if      (c3 >= rem)           { sel = 3u; }
            else if (c3 + c2 >= rem)      { sel = 2u; rem -= c3; }
            else if (c3 + c2 + c1 >= rem) { sel = 1u; rem -= c3 + c2; }
            else                          { sel = 0u; rem -= c3 + c2 + c1; }
            prefix |= sel << bit;
            pmask  |= 3u << bit;
        }
        vstar  = prefix;
        r_ties = rem;
    }

    // stable tie rank: warp-exclusive scan of per-lane tie counts
    int myt = 0;
    for (int k = 0; k < 512; k++) myt += (vrow[lane * 512 + k] == vstar);
    int ts = myt;
#pragma unroll
    for (int off = 1; off < 32; off <<= 1) {
        const int n = __shfl_up_sync(FULL, ts, off);
        if (lane >= off) ts += n;
    }
    int tie_idx = ts - myt;   // exclusive base

    for (int k = 0; k < 512; k++) {
        const int a = lane * 512 + k;
        const uint32_t v = vrow[a];
        const bool tie = (v == vstar);
        const bool neg = (v > vstar) || (tie && tie_idx < r_ties);
        if (tie) tie_idx++;
        const bool pos = (pw[k >> 5] >> (a & 31)) & 1u;
        if (!(pos || neg)) {
            float* row = out + ((size_t)b * A + a) * C;
            for (int c = 0; c < C; c++) row[c] = 0.0f;
        }
    }
}

// ---------------------------------------------------------------------------
extern "C" void kernel_launch(void* const* d_in, const int* in_sizes, int n_in,
                              void* d_out, int out_size)
{
    const float* pred  = (const float*)d_in[0];
    const float* tgt   = (const float*)d_in[1];
    const int*   depth = (const int*)d_in[2];
    const int*   npr   = (n_in >= 4) ? (const int*)d_in[3] : nullptr;
    float* out = (float*)d_out;

    ce_kernel<<<(B * A) / APB, 256>>>(pred, tgt, depth, out);

    // Programmatic dependent launch: mask waits in-kernel; launch overlaps
    // ce's tail.
    cudaLaunchAttribute attrs[1];
    attrs[0].id = cudaLaunchAttributeProgrammaticStreamSerialization;
    attrs[0].val.programmaticStreamSerializationAllowed = 1;
    cudaLaunchConfig_t cfg = {};
    cfg.gridDim  = dim3(B, 1, 1);
    cfg.blockDim = dim3(32, 1, 1);
    cfg.dynamicSmemBytes = 0;
    cfg.stream = 0;
    cfg.attrs = attrs;
    cfg.numAttrs = 1;
    cudaLaunchKernelEx(&cfg, mask_kernel, npr, out);
}